// round 1
// baseline (speedup 1.0000x reference)
#include <cuda_runtime.h>

#define E_MAX 20000
#define FD 128
#define H1D 64
#define H2D 32
#define DD 16
#define LN_EPS 1e-5f

// Scratch: precomputed A = ef@W1[:128] + b1, B = ef@W1[128:]
__device__ float g_A[E_MAX * H1D];
__device__ float g_B[E_MAX * H1D];

// ---------------------------------------------------------------------------
// Precompute per-edge partial layer-1 outputs. blockDim = (64, 4): 4 edges per
// block, one thread per (edge, output-channel).
// ---------------------------------------------------------------------------
__global__ void precompute_kernel(const float* __restrict__ ef,
                                  const float* __restrict__ W1,
                                  const float* __restrict__ b1,
                                  int E) {
    __shared__ float efs[4][FD];
    const int tx = threadIdx.x;          // output channel 0..63
    const int ty = threadIdx.y;          // local edge 0..3
    const int tid = ty * 64 + tx;
    const int e0 = blockIdx.x * 4;

    for (int idx = tid; idx < 4 * FD; idx += 256) {
        int le = idx >> 7;
        int k  = idx & (FD - 1);
        int e  = e0 + le;
        efs[le][k] = (e < E) ? ef[e * FD + k] : 0.f;
    }
    __syncthreads();

    const int e = e0 + ty;
    if (e >= E) return;

    float a = b1[tx];
    float b = 0.f;
#pragma unroll 8
    for (int k = 0; k < FD; ++k) {
        float s = efs[ty][k];
        a = fmaf(s, W1[k * H1D + tx], a);
        b = fmaf(s, W1[(FD + k) * H1D + tx], b);
    }
    g_A[e * H1D + tx] = a;
    g_B[e * H1D + tx] = b;
}

// ---------------------------------------------------------------------------
// Main kernel: one thread per pair. Gather A[i]+B[j] -> LN -> ReLU ->
// W2 matvec -> LN -> ReLU -> W3 matvec -> stage diag in smem ->
// cooperative fully-coalesced streaming stores of the [16,16] diag-embed.
// ---------------------------------------------------------------------------
__global__ void __launch_bounds__(256)
pairs_kernel(const int* __restrict__ pi, const int* __restrict__ pj,
             const float* __restrict__ g1, const float* __restrict__ be1,
             const float* __restrict__ W2, const float* __restrict__ b2,
             const float* __restrict__ g2, const float* __restrict__ be2,
             const float* __restrict__ W3, const float* __restrict__ b3,
             float* __restrict__ out, int P) {
    __shared__ float W2s[H1D * H2D];     // 8 KB
    __shared__ float W3s[H2D * DD];      // 2 KB
    __shared__ float g1s[H1D], be1s[H1D];
    __shared__ float b2s[H2D], g2s[H2D], be2s[H2D], b3s[DD];
    __shared__ float diag[256][DD];      // 16 KB

    const int tid = threadIdx.x;

    for (int idx = tid; idx < H1D * H2D; idx += 256) W2s[idx] = W2[idx];
    for (int idx = tid; idx < H2D * DD; idx += 256) W3s[idx] = W3[idx];
    if (tid < H1D) { g1s[tid] = g1[tid]; be1s[tid] = be1[tid]; }
    if (tid < H2D) { b2s[tid] = b2[tid]; g2s[tid] = g2[tid]; be2s[tid] = be2[tid]; }
    if (tid < DD)  { b3s[tid] = b3[tid]; }
    __syncthreads();

    const int p = blockIdx.x * 256 + tid;
    float pr[DD];

    if (p < P) {
        const int i = pi[p];
        const int j = pj[p];
        float h1[H1D];
        const float4* a4 = reinterpret_cast<const float4*>(g_A + (size_t)i * H1D);
        const float4* b4 = reinterpret_cast<const float4*>(g_B + (size_t)j * H1D);
#pragma unroll
        for (int q = 0; q < H1D / 4; ++q) {
            float4 av = a4[q];
            float4 bv = b4[q];
            h1[4 * q + 0] = av.x + bv.x;
            h1[4 * q + 1] = av.y + bv.y;
            h1[4 * q + 2] = av.z + bv.z;
            h1[4 * q + 3] = av.w + bv.w;
        }
        // LayerNorm over 64 + affine + ReLU
        float mu = 0.f;
#pragma unroll
        for (int k = 0; k < H1D; ++k) mu += h1[k];
        mu *= (1.f / H1D);
        float var = 0.f;
#pragma unroll
        for (int k = 0; k < H1D; ++k) { float d = h1[k] - mu; var = fmaf(d, d, var); }
        var *= (1.f / H1D);
        float inv = rsqrtf(var + LN_EPS);
#pragma unroll
        for (int k = 0; k < H1D; ++k) {
            float v = fmaf((h1[k] - mu) * inv, g1s[k], be1s[k]);
            h1[k] = fmaxf(v, 0.f);
        }
        // Layer 2: [64] x [64,32]
        float h2[H2D];
#pragma unroll
        for (int o = 0; o < H2D; ++o) h2[o] = b2s[o];
#pragma unroll
        for (int k = 0; k < H1D; ++k) {
            float t = h1[k];
#pragma unroll
            for (int o = 0; o < H2D; ++o) h2[o] = fmaf(t, W2s[k * H2D + o], h2[o]);
        }
        // LayerNorm over 32 + affine + ReLU
        float mu2 = 0.f;
#pragma unroll
        for (int k = 0; k < H2D; ++k) mu2 += h2[k];
        mu2 *= (1.f / H2D);
        float var2 = 0.f;
#pragma unroll
        for (int k = 0; k < H2D; ++k) { float d = h2[k] - mu2; var2 = fmaf(d, d, var2); }
        var2 *= (1.f / H2D);
        float inv2 = rsqrtf(var2 + LN_EPS);
#pragma unroll
        for (int k = 0; k < H2D; ++k) {
            float v = fmaf((h2[k] - mu2) * inv2, g2s[k], be2s[k]);
            h2[k] = fmaxf(v, 0.f);
        }
        // Layer 3: [32] x [32,16]
#pragma unroll
        for (int o = 0; o < DD; ++o) pr[o] = b3s[o];
#pragma unroll
        for (int k = 0; k < H2D; ++k) {
            float t = h2[k];
#pragma unroll
            for (int o = 0; o < DD; ++o) pr[o] = fmaf(t, W3s[k * DD + o], pr[o]);
        }
    } else {
#pragma unroll
        for (int o = 0; o < DD; ++o) pr[o] = 0.f;
    }

#pragma unroll
    for (int o = 0; o < DD; ++o) diag[tid][o] = pr[o];
    __syncthreads();

    // Cooperative coalesced store of the diag-embedded [256 pairs, 16, 16] tile.
    // Per pair: 256 floats = 64 float4. Block covers 256*64 = 16384 float4.
    const size_t blockBase4 = (size_t)blockIdx.x * (256 * 64);
    const size_t total4 = (size_t)P * 64;
    float4* o4 = reinterpret_cast<float4*>(out);
#pragma unroll 4
    for (int it = 0; it < 64; ++it) {
        const int local4 = it * 256 + tid;           // 0..16383
        const size_t f4 = blockBase4 + local4;
        if (f4 < total4) {
            const int lp = local4 >> 6;              // local pair (64 float4 each)
            const int w4 = local4 & 63;              // float4 index within pair
            const int row = w4 >> 2;                 // 4 float4 per 16-float row
            const int col0 = (w4 & 3) * 4;
            float4 v = make_float4(0.f, 0.f, 0.f, 0.f);
            const int d = row - col0;
            if (d >= 0 && d < 4) {
                reinterpret_cast<float*>(&v)[d] = diag[lp][row];
            }
            __stcs(o4 + f4, v);
        }
    }
}

extern "C" void kernel_launch(void* const* d_in, const int* in_sizes, int n_in,
                              void* d_out, int out_size) {
    const float* ef  = (const float*)d_in[0];
    const int*   pi  = (const int*)d_in[1];
    const int*   pj  = (const int*)d_in[2];
    const float* W1  = (const float*)d_in[3];
    const float* b1  = (const float*)d_in[4];
    const float* g1  = (const float*)d_in[5];
    const float* be1 = (const float*)d_in[6];
    const float* W2  = (const float*)d_in[7];
    const float* b2  = (const float*)d_in[8];
    const float* g2  = (const float*)d_in[9];
    const float* be2 = (const float*)d_in[10];
    const float* W3  = (const float*)d_in[11];
    const float* b3  = (const float*)d_in[12];
    float* out = (float*)d_out;

    const int E = in_sizes[0] / FD;
    const int P = in_sizes[1];

    dim3 pb(64, 4);
    precompute_kernel<<<(E + 3) / 4, pb>>>(ef, W1, b1, E);

    const int blocks = (P + 255) / 256;
    pairs_kernel<<<blocks, 256>>>(pi, pj, g1, be1, W2, b2, g2, be2, W3, b3, out, P);
}